// round 9
// baseline (speedup 1.0000x reference)
#include <cuda_runtime.h>
#include <math.h>
#include <stdint.h>

#define TT 2048
#define BB 64
#define KIN 256
#define HH 256

typedef unsigned long long ull;

// Scratch for precomputed input projection xp[t][b][h] (134 MB device global).
__device__ float g_xp[(size_t)TT * BB * HH];

// ---------------------------------------------------------------------------
// f32x2 helpers (Blackwell packed fp32 pipe)
// ---------------------------------------------------------------------------
__device__ __forceinline__ ull ffma2(ull a, ull b, ull c) {
    ull d;
    asm("fma.rn.f32x2 %0, %1, %2, %3;" : "=l"(d) : "l"(a), "l"(b), "l"(c));
    return d;
}
__device__ __forceinline__ ull fdup2(float a) {
    ull d; unsigned u = __float_as_uint(a);
    asm("mov.b64 %0, {%1, %2};" : "=l"(d) : "r"(u), "r"(u));
    return d;
}
__device__ __forceinline__ float2 funpack2(ull a) {
    unsigned lo, hi;
    asm("mov.b64 {%0, %1}, %2;" : "=r"(lo), "=r"(hi) : "l"(a));
    return make_float2(__uint_as_float(lo), __uint_as_float(hi));
}
__device__ __forceinline__ uint32_t smem_u32(const void* p) {
    uint32_t a;
    asm("{ .reg .u64 t; cvta.to.shared.u64 t, %1; cvt.u32.u64 %0, t; }"
        : "=r"(a) : "l"(p));
    return a;
}
__device__ __forceinline__ uint32_t mapa_peer(uint32_t local, uint32_t peer) {
    uint32_t r;
    asm("mapa.shared::cluster.u32 %0, %1, %2;" : "=r"(r) : "r"(local), "r"(peer));
    return r;
}
__device__ __forceinline__ void st_async_b32(uint32_t raddr, float v, uint32_t rbar) {
    asm volatile(
        "st.async.shared::cluster.mbarrier::complete_tx::bytes.b32 [%0], %1, [%2];"
        :: "r"(raddr), "f"(v), "r"(rbar) : "memory");
}
__device__ __forceinline__ void mbar_init(uint32_t addr, uint32_t cnt) {
    asm volatile("mbarrier.init.shared.b64 [%0], %1;" :: "r"(addr), "r"(cnt) : "memory");
}
__device__ __forceinline__ void mbar_expect_tx(uint32_t addr, uint32_t bytes) {
    asm volatile("mbarrier.arrive.expect_tx.shared.b64 _, [%0], %1;"
                 :: "r"(addr), "r"(bytes) : "memory");
}
__device__ __forceinline__ void mbar_wait_parity(uint32_t addr, uint32_t parity) {
    asm volatile(
        "{\n\t"
        ".reg .pred P;\n\t"
        "WL_%=:\n\t"
        "mbarrier.try_wait.parity.acquire.cluster.shared::cta.b64 P, [%0], %1, 0x989680;\n\t"
        "@!P bra WL_%=;\n\t"
        "}" :: "r"(addr), "r"(parity) : "memory");
}
#define CLUSTER_SYNC_() do { \
    asm volatile("barrier.cluster.arrive.aligned;" ::: "memory"); \
    asm volatile("barrier.cluster.wait.aligned;" ::: "memory"); \
} while (0)

// ---------------------------------------------------------------------------
// Kernel 1: xp[m][n] = x[m][:] . W_ih[n][:] + b_ih[n] + b_hh[n]   (f32x2 GEMM)
// (unchanged from round 8)
// ---------------------------------------------------------------------------
__global__ __launch_bounds__(256, 2) void xp_gemm_kernel(
    const float* __restrict__ x,
    const float* __restrict__ Wih,
    const float* __restrict__ b_ih,
    const float* __restrict__ b_hh)
{
    __shared__ __align__(16) float As[16][132];
    __shared__ __align__(16) float Bs[16][132];

    const int tid = threadIdx.x;
    const int m0 = blockIdx.x * 128;
    const int n0 = blockIdx.y * 128;
    const int ty = tid >> 4;
    const int tx = tid & 15;

    ull acc[8][4];
#pragma unroll
    for (int i = 0; i < 8; i++)
#pragma unroll
        for (int p = 0; p < 4; p++) acc[i][p] = 0ull;

    for (int kt = 0; kt < KIN; kt += 16) {
#pragma unroll
        for (int l = 0; l < 2; l++) {
            int id  = tid + l * 256;
            int row = id >> 2;
            int c4  = (id & 3) * 4;
            float4 av = *(const float4*)(x   + (size_t)(m0 + row) * KIN + kt + c4);
            As[c4 + 0][row] = av.x; As[c4 + 1][row] = av.y;
            As[c4 + 2][row] = av.z; As[c4 + 3][row] = av.w;
            float4 bv = *(const float4*)(Wih + (size_t)(n0 + row) * KIN + kt + c4);
            Bs[c4 + 0][row] = bv.x; Bs[c4 + 1][row] = bv.y;
            Bs[c4 + 2][row] = bv.z; Bs[c4 + 3][row] = bv.w;
        }
        __syncthreads();

#pragma unroll
        for (int k = 0; k < 16; k++) {
            float4 a03 = *(const float4*)&As[k][ty * 8];
            float4 a47 = *(const float4*)&As[k][ty * 8 + 4];
            ulonglong2 bq0 = *(const ulonglong2*)&Bs[k][tx * 8];
            ulonglong2 bq1 = *(const ulonglong2*)&Bs[k][tx * 8 + 4];
            ull bp[4] = { bq0.x, bq0.y, bq1.x, bq1.y };
            float av[8] = { a03.x, a03.y, a03.z, a03.w, a47.x, a47.y, a47.z, a47.w };
#pragma unroll
            for (int i = 0; i < 8; i++) {
                ull ad = fdup2(av[i]);
#pragma unroll
                for (int p = 0; p < 4; p++)
                    acc[i][p] = ffma2(ad, bp[p], acc[i][p]);
            }
        }
        __syncthreads();
    }

    float bb[8];
#pragma unroll
    for (int j = 0; j < 8; j++) {
        int n = n0 + tx * 8 + j;
        bb[j] = b_ih[n] + b_hh[n];
    }
#pragma unroll
    for (int i = 0; i < 8; i++) {
        float* dst = g_xp + (size_t)(m0 + ty * 8 + i) * HH + n0 + tx * 8;
        float2 c0 = funpack2(acc[i][0]);
        float2 c1 = funpack2(acc[i][1]);
        float2 c2 = funpack2(acc[i][2]);
        float2 c3 = funpack2(acc[i][3]);
        float4 v0 = make_float4(c0.x + bb[0], c0.y + bb[1], c1.x + bb[2], c1.y + bb[3]);
        float4 v1 = make_float4(c2.x + bb[4], c2.y + bb[5], c3.x + bb[6], c3.y + bb[7]);
        *(float4*)dst       = v0;
        *(float4*)(dst + 4) = v1;
    }
}

// ---------------------------------------------------------------------------
// Kernel 2: serial recurrence. Cluster of 2 CTAs per batch (grid 128).
// CTA rank r owns rows [128r, 128r+128). 512 thr: jg=tid>>3 (rows 2jg,2jg+1),
// c=tid&7. Lane's K coverage = local chunk [16*(rank*8+c), +16) from own-CTA
// h + remote chunk [16*(peer*8+c), +16) delivered by peer st.async.
// Step: expect -> LOCAL FMA (no wait) -> deferred wait for prev step's peer
// bytes -> REMOTE FMA -> 3-round shfl reduce -> tanh split on c==0/c==1 ->
// stores + st.async -> __syncthreads. Two mbarriers alternated by t&1
// (phase flips per 2 uses). h buffers padded: 16-float chunks at 20-float
// stride -> conflict-free LDS.128.
// ---------------------------------------------------------------------------
#define HPAD 20                       // floats per 16-float chunk (padded)
#define HBUF (16 * HPAD)              // 320 floats per h buffer

__global__ __launch_bounds__(512, 1) __cluster_dims__(2, 1, 1)
void rnn_scan_kernel(const float* __restrict__ Whh, float* __restrict__ out)
{
    __shared__ __align__(16) float hsm[2][HBUF];
    __shared__ __align__(8)  ull   mbars[2];

    const int tid = threadIdx.x;
    const unsigned rank = blockIdx.x & 1u;
    const int batch = blockIdx.x >> 1;
    const int c  = tid & 7;
    const int jg = tid >> 3;
    const int j0 = (int)rank * 128 + 2 * jg;       // even global row
    const int Lc = (int)rank * 8 + c;              // local K-chunk index
    const int Rc = (int)(rank ^ 1u) * 8 + c;       // remote K-chunk index

    const uint32_t mb0 = smem_u32(&mbars[0]);
    const uint32_t mb1 = smem_u32(&mbars[1]);
    const uint32_t hsm_addr = smem_u32(&hsm[0][0]);
    const uint32_t peer = rank ^ 1u;
    const uint32_t peer_mb0 = mapa_peer(mb0, peer);
    const uint32_t peer_mb1 = mapa_peer(mb1, peer);
    const uint32_t peer_hsm = mapa_peer(hsm_addr, peer);

    // Register-resident W: rows j0, j0+1 x (local 16 + remote 16) K as ull pairs.
    ull wl0[8], wl1[8], wr0[8], wr1[8];
    {
        const ull* p;
        p = (const ull*)(Whh + (size_t)j0 * HH + 16 * Lc);
#pragma unroll
        for (int i = 0; i < 8; i++) wl0[i] = p[i];
        p = (const ull*)(Whh + (size_t)(j0 + 1) * HH + 16 * Lc);
#pragma unroll
        for (int i = 0; i < 8; i++) wl1[i] = p[i];
        p = (const ull*)(Whh + (size_t)j0 * HH + 16 * Rc);
#pragma unroll
        for (int i = 0; i < 8; i++) wr0[i] = p[i];
        p = (const ull*)(Whh + (size_t)(j0 + 1) * HH + 16 * Rc);
#pragma unroll
        for (int i = 0; i < 8; i++) wr1[i] = p[i];
    }

    if (tid < HBUF) hsm[0][tid] = 0.0f;            // h_{-1} = 0 (both halves)
    if (tid == 0) { mbar_init(mb0, 1); mbar_init(mb1, 1); }
    __syncthreads();
    CLUSTER_SYNC_();                                // peer mbars visible

    const size_t tstride = (size_t)BB * HH;
    // Per-lane scalar row (only meaningful for c < 2): row j0 + c.
    const float* xpp  = g_xp + (size_t)batch * HH + j0 + c;
    float*       outp = out  + (size_t)batch * HH + j0 + c;

    float xv = 0.0f;
    if (c < 2) xv = *xpp;                           // xp for t = 0

    for (int t = 0; t < TT; t++) {
        const unsigned par = (unsigned)t & 1u;
        const uint32_t mbar      = par ? mb1 : mb0;
        const uint32_t peer_mbar = par ? peer_mb1 : peer_mb0;

        if (tid == 0) mbar_expect_tx(mbar, 512);    // this step's 128 x 4 B

        // ---- LOCAL half: own-CTA h, guarded by last step's __syncthreads ----
        const ulonglong2* hl = (const ulonglong2*)&hsm[par][HPAD * Lc];
        ull a0 = 0ull, a1 = 0ull;
#pragma unroll
        for (int i = 0; i < 4; i++) {
            ulonglong2 hq = hl[i];
            a0 = ffma2(wl0[2 * i],     hq.x, a0);
            a1 = ffma2(wl1[2 * i],     hq.x, a1);
            a0 = ffma2(wl0[2 * i + 1], hq.y, a0);
            a1 = ffma2(wl1[2 * i + 1], hq.y, a1);
        }

        // ---- deferred wait: previous step's peer bytes (buffer par, remote) ----
        if (t > 0) {
            const unsigned pw = (unsigned)(t - 1) & 1u;
            mbar_wait_parity(pw ? mb1 : mb0, ((unsigned)(t - 1) >> 1) & 1u);
        }

        // ---- REMOTE half ----
        const ulonglong2* hr = (const ulonglong2*)&hsm[par][HPAD * Rc];
#pragma unroll
        for (int i = 0; i < 4; i++) {
            ulonglong2 hq = hr[i];
            a0 = ffma2(wr0[2 * i],     hq.x, a0);
            a1 = ffma2(wr1[2 * i],     hq.x, a1);
            a0 = ffma2(wr0[2 * i + 1], hq.y, a0);
            a1 = ffma2(wr1[2 * i + 1], hq.y, a1);
        }

        float2 u0 = funpack2(a0), u1 = funpack2(a1);
        float s0 = u0.x + u0.y;
        float s1 = u1.x + u1.y;
#pragma unroll
        for (int m = 1; m < 8; m <<= 1) {
            s0 += __shfl_xor_sync(0xffffffffu, s0, m);
            s1 += __shfl_xor_sync(0xffffffffu, s1, m);
        }

        if (c < 2) {                                // lane c: row j0+c
            const int j = j0 + c;
            float hn = tanhf((c ? s1 : s0) + xv);
            const unsigned nb = par ^ 1u;
            const unsigned idx = (unsigned)(HPAD * (j >> 4) + (j & 15));
            hsm[nb][idx] = hn;                      // local publish (next step)
            st_async_b32(peer_hsm + (nb * (unsigned)HBUF + idx) * 4u,
                         hn, peer_mbar);            // remote publish + tx
            outp[(size_t)t * tstride] = hn;         // output
            if (t + 1 < TT)
                xv = xpp[(size_t)(t + 1) * tstride];  // prefetch next xp
        }

        __syncthreads();                            // publish local h CTA-wide
    }

    // Retire the final step's in-flight st.asyncs before the CTAs exit.
    mbar_wait_parity(((TT - 1) & 1) ? mb1 : mb0, ((TT - 1) >> 1) & 1u);
    CLUSTER_SYNC_();
}

// ---------------------------------------------------------------------------
// Launch
// ---------------------------------------------------------------------------
extern "C" void kernel_launch(void* const* d_in, const int* in_sizes, int n_in,
                              void* d_out, int out_size)
{
    const float* x    = (const float*)d_in[0];
    const float* Wih  = (const float*)d_in[1];
    const float* Whh  = (const float*)d_in[2];
    const float* b_ih = (const float*)d_in[3];
    const float* b_hh = (const float*)d_in[4];
    float* out = (float*)d_out;

    dim3 g1((TT * BB) / 128, HH / 128);
    xp_gemm_kernel<<<g1, 256>>>(x, Wih, b_ih, b_hh);

    rnn_scan_kernel<<<2 * BB, 512>>>(Whh, out);
}

// round 10
// speedup vs baseline: 1.4198x; 1.4198x over previous
#include <cuda_runtime.h>
#include <math.h>
#include <stdint.h>

#define TT 2048
#define BB 64
#define KIN 256
#define HH 256

typedef unsigned long long ull;

// Scratch for precomputed input projection xp[t][b][h] (134 MB device global).
__device__ float g_xp[(size_t)TT * BB * HH];

// ---------------------------------------------------------------------------
// f32x2 helpers (Blackwell packed fp32 pipe)
// ---------------------------------------------------------------------------
__device__ __forceinline__ ull ffma2(ull a, ull b, ull c) {
    ull d;
    asm("fma.rn.f32x2 %0, %1, %2, %3;" : "=l"(d) : "l"(a), "l"(b), "l"(c));
    return d;
}
__device__ __forceinline__ ull fdup2(float a) {
    ull d; unsigned u = __float_as_uint(a);
    asm("mov.b64 %0, {%1, %2};" : "=l"(d) : "r"(u), "r"(u));
    return d;
}
__device__ __forceinline__ ull fpack2(float a, float b) {
    ull d;
    asm("mov.b64 %0, {%1, %2};" : "=l"(d)
        : "r"(__float_as_uint(a)), "r"(__float_as_uint(b)));
    return d;
}
__device__ __forceinline__ float2 funpack2(ull a) {
    unsigned lo, hi;
    asm("mov.b64 {%0, %1}, %2;" : "=r"(lo), "=r"(hi) : "l"(a));
    return make_float2(__uint_as_float(lo), __uint_as_float(hi));
}
__device__ __forceinline__ uint32_t smem_u32(const void* p) {
    uint32_t a;
    asm("{ .reg .u64 t; cvta.to.shared.u64 t, %1; cvt.u32.u64 %0, t; }"
        : "=r"(a) : "l"(p));
    return a;
}
__device__ __forceinline__ uint32_t mapa_peer(uint32_t local, uint32_t peer) {
    uint32_t r;
    asm("mapa.shared::cluster.u32 %0, %1, %2;" : "=r"(r) : "r"(local), "r"(peer));
    return r;
}
__device__ __forceinline__ void st_async_b64(uint32_t raddr, ull v, uint32_t rbar) {
    asm volatile(
        "st.async.shared::cluster.mbarrier::complete_tx::bytes.b64 [%0], %1, [%2];"
        :: "r"(raddr), "l"(v), "r"(rbar) : "memory");
}
__device__ __forceinline__ void mbar_init(uint32_t addr, uint32_t cnt) {
    asm volatile("mbarrier.init.shared.b64 [%0], %1;" :: "r"(addr), "r"(cnt) : "memory");
}
__device__ __forceinline__ void mbar_expect_tx(uint32_t addr, uint32_t bytes) {
    asm volatile("mbarrier.arrive.expect_tx.shared.b64 _, [%0], %1;"
                 :: "r"(addr), "r"(bytes) : "memory");
}
__device__ __forceinline__ void mbar_wait_parity(uint32_t addr, uint32_t parity) {
    asm volatile(
        "{\n\t"
        ".reg .pred P;\n\t"
        "WL_%=:\n\t"
        "mbarrier.try_wait.parity.acquire.cluster.shared::cta.b64 P, [%0], %1, 0x989680;\n\t"
        "@!P bra WL_%=;\n\t"
        "}" :: "r"(addr), "r"(parity) : "memory");
}
#define CLUSTER_SYNC_() do { \
    asm volatile("barrier.cluster.arrive.aligned;" ::: "memory"); \
    asm volatile("barrier.cluster.wait.aligned;" ::: "memory"); \
} while (0)

// ---------------------------------------------------------------------------
// Kernel 1: xp[m][n] = x[m][:] . W_ih[n][:] + b_ih[n] + b_hh[n]   (f32x2 GEMM)
// (unchanged: proven)
// ---------------------------------------------------------------------------
__global__ __launch_bounds__(256, 2) void xp_gemm_kernel(
    const float* __restrict__ x,
    const float* __restrict__ Wih,
    const float* __restrict__ b_ih,
    const float* __restrict__ b_hh)
{
    __shared__ __align__(16) float As[16][132];
    __shared__ __align__(16) float Bs[16][132];

    const int tid = threadIdx.x;
    const int m0 = blockIdx.x * 128;
    const int n0 = blockIdx.y * 128;
    const int ty = tid >> 4;
    const int tx = tid & 15;

    ull acc[8][4];
#pragma unroll
    for (int i = 0; i < 8; i++)
#pragma unroll
        for (int p = 0; p < 4; p++) acc[i][p] = 0ull;

    for (int kt = 0; kt < KIN; kt += 16) {
#pragma unroll
        for (int l = 0; l < 2; l++) {
            int id  = tid + l * 256;
            int row = id >> 2;
            int c4  = (id & 3) * 4;
            float4 av = *(const float4*)(x   + (size_t)(m0 + row) * KIN + kt + c4);
            As[c4 + 0][row] = av.x; As[c4 + 1][row] = av.y;
            As[c4 + 2][row] = av.z; As[c4 + 3][row] = av.w;
            float4 bv = *(const float4*)(Wih + (size_t)(n0 + row) * KIN + kt + c4);
            Bs[c4 + 0][row] = bv.x; Bs[c4 + 1][row] = bv.y;
            Bs[c4 + 2][row] = bv.z; Bs[c4 + 3][row] = bv.w;
        }
        __syncthreads();

#pragma unroll
        for (int k = 0; k < 16; k++) {
            float4 a03 = *(const float4*)&As[k][ty * 8];
            float4 a47 = *(const float4*)&As[k][ty * 8 + 4];
            ulonglong2 bq0 = *(const ulonglong2*)&Bs[k][tx * 8];
            ulonglong2 bq1 = *(const ulonglong2*)&Bs[k][tx * 8 + 4];
            ull bp[4] = { bq0.x, bq0.y, bq1.x, bq1.y };
            float av[8] = { a03.x, a03.y, a03.z, a03.w, a47.x, a47.y, a47.z, a47.w };
#pragma unroll
            for (int i = 0; i < 8; i++) {
                ull ad = fdup2(av[i]);
#pragma unroll
                for (int p = 0; p < 4; p++)
                    acc[i][p] = ffma2(ad, bp[p], acc[i][p]);
            }
        }
        __syncthreads();
    }

    float bb[8];
#pragma unroll
    for (int j = 0; j < 8; j++) {
        int n = n0 + tx * 8 + j;
        bb[j] = b_ih[n] + b_hh[n];
    }
#pragma unroll
    for (int i = 0; i < 8; i++) {
        float* dst = g_xp + (size_t)(m0 + ty * 8 + i) * HH + n0 + tx * 8;
        float2 c0 = funpack2(acc[i][0]);
        float2 c1 = funpack2(acc[i][1]);
        float2 c2 = funpack2(acc[i][2]);
        float2 c3 = funpack2(acc[i][3]);
        float4 v0 = make_float4(c0.x + bb[0], c0.y + bb[1], c1.x + bb[2], c1.y + bb[3]);
        float4 v1 = make_float4(c2.x + bb[4], c2.y + bb[5], c3.x + bb[6], c3.y + bb[7]);
        *(float4*)dst       = v0;
        *(float4*)(dst + 4) = v1;
    }
}

// ---------------------------------------------------------------------------
// Kernel 2: serial recurrence. Cluster of 2 CTAs per batch (grid 128).
// ROUND-8 BASE (64 x 8 B st.async, c==0 lane does both tanhs + one b64 send)
// + DEFERRED WAIT: lane covers local K chunk [16*(rank*8+c),+16) (own-CTA h)
// and remote chunk [16*(peer*8+c),+16) (peer-delivered). Step:
//   expect -> local FMA -> wait(prev step's peer bytes) -> remote FMA ->
//   reduce -> tanh -> stores + st.async -> __syncthreads
// Two mbarriers alternated by t&1; phase flips every 2 uses.
// h buffers: 16-float chunks at 20-float stride -> conflict-free LDS.128.
// ---------------------------------------------------------------------------
#define HPAD 20                       // floats per 16-float chunk (padded)
#define HBUF (16 * HPAD)              // 320 floats per h buffer

__global__ __launch_bounds__(512, 1) __cluster_dims__(2, 1, 1)
void rnn_scan_kernel(const float* __restrict__ Whh, float* __restrict__ out)
{
    __shared__ __align__(16) float hsm[2][HBUF];
    __shared__ __align__(8)  ull   mbars[2];

    const int tid = threadIdx.x;
    const unsigned rank = blockIdx.x & 1u;
    const int batch = blockIdx.x >> 1;
    const int c  = tid & 7;
    const int jg = tid >> 3;
    const int j0 = (int)rank * 128 + 2 * jg;       // even global row
    const int Lc = (int)rank * 8 + c;              // local K-chunk index
    const int Rc = (int)(rank ^ 1u) * 8 + c;       // remote K-chunk index
    // padded slot of row pair (j0, j0+1)
    const unsigned wofs = (unsigned)(HPAD * (j0 >> 4) + (j0 & 15));

    const uint32_t mb0 = smem_u32(&mbars[0]);
    const uint32_t mb1 = smem_u32(&mbars[1]);
    const uint32_t hsm_addr = smem_u32(&hsm[0][0]);
    const uint32_t peer = rank ^ 1u;
    const uint32_t peer_mb0 = mapa_peer(mb0, peer);
    const uint32_t peer_mb1 = mapa_peer(mb1, peer);
    const uint32_t peer_hsm = mapa_peer(hsm_addr, peer);

    // Register-resident W: rows j0, j0+1 x (local 16 + remote 16) K as ull pairs.
    ull wl0[8], wl1[8], wr0[8], wr1[8];
    {
        const ull* p;
        p = (const ull*)(Whh + (size_t)j0 * HH + 16 * Lc);
#pragma unroll
        for (int i = 0; i < 8; i++) wl0[i] = p[i];
        p = (const ull*)(Whh + (size_t)(j0 + 1) * HH + 16 * Lc);
#pragma unroll
        for (int i = 0; i < 8; i++) wl1[i] = p[i];
        p = (const ull*)(Whh + (size_t)j0 * HH + 16 * Rc);
#pragma unroll
        for (int i = 0; i < 8; i++) wr0[i] = p[i];
        p = (const ull*)(Whh + (size_t)(j0 + 1) * HH + 16 * Rc);
#pragma unroll
        for (int i = 0; i < 8; i++) wr1[i] = p[i];
    }

    if (tid < HBUF) hsm[0][tid] = 0.0f;            // h_{-1} = 0 (all chunks)
    if (tid == 0) { mbar_init(mb0, 1); mbar_init(mb1, 1); }
    __syncthreads();
    CLUSTER_SYNC_();                                // peer mbars visible

    const size_t tstride = (size_t)BB * HH;
    const float* xpp  = g_xp + (size_t)batch * HH + j0;
    float*       outp = out  + (size_t)batch * HH + j0;

    float2 xv = make_float2(0.f, 0.f);
    if (c == 0) xv = *(const float2*)xpp;           // xp for t = 0

    for (int t = 0; t < TT; t++) {
        const unsigned par = (unsigned)t & 1u;
        const uint32_t mbar      = par ? mb1 : mb0;
        const uint32_t peer_mbar = par ? peer_mb1 : peer_mb0;

        if (tid == 0) mbar_expect_tx(mbar, 512);    // step t sends: 64 x 8 B

        // ---- LOCAL half: own-CTA h, guarded by last step's __syncthreads ----
        const ulonglong2* hl = (const ulonglong2*)&hsm[par][HPAD * Lc];
        ull a0 = 0ull, a1 = 0ull;
#pragma unroll
        for (int i = 0; i < 4; i++) {
            ulonglong2 hq = hl[i];
            a0 = ffma2(wl0[2 * i],     hq.x, a0);
            a1 = ffma2(wl1[2 * i],     hq.x, a1);
            a0 = ffma2(wl0[2 * i + 1], hq.y, a0);
            a1 = ffma2(wl1[2 * i + 1], hq.y, a1);
        }

        // ---- deferred wait: previous step's peer deliveries into buffer par ----
        if (t > 0) {
            const unsigned pw = (unsigned)(t - 1) & 1u;
            mbar_wait_parity(pw ? mb1 : mb0, ((unsigned)(t - 1) >> 1) & 1u);
        }

        // ---- REMOTE half (separate accumulators -> shorter dep chains) ----
        const ulonglong2* hr = (const ulonglong2*)&hsm[par][HPAD * Rc];
        ull b0 = 0ull, b1 = 0ull;
#pragma unroll
        for (int i = 0; i < 4; i++) {
            ulonglong2 hq = hr[i];
            b0 = ffma2(wr0[2 * i],     hq.x, b0);
            b1 = ffma2(wr1[2 * i],     hq.x, b1);
            b0 = ffma2(wr0[2 * i + 1], hq.y, b0);
            b1 = ffma2(wr1[2 * i + 1], hq.y, b1);
        }

        float2 u0 = funpack2(a0), u1 = funpack2(a1);
        float2 v0 = funpack2(b0), v1 = funpack2(b1);
        float s0 = (u0.x + u0.y) + (v0.x + v0.y);
        float s1 = (u1.x + u1.y) + (v1.x + v1.y);
#pragma unroll
        for (int m = 1; m < 8; m <<= 1) {
            s0 += __shfl_xor_sync(0xffffffffu, s0, m);
            s1 += __shfl_xor_sync(0xffffffffu, s1, m);
        }

        if (c == 0) {
            float h0 = tanhf(s0 + xv.x);
            float h1 = tanhf(s1 + xv.y);
            const unsigned nb = par ^ 1u;
            // local publish into next buffer (padded layout)
            *(float2*)&hsm[nb][wofs] = make_float2(h0, h1);
            // remote publish + tx on peer's mbar[par]
            st_async_b64(peer_hsm + (nb * (unsigned)HBUF + wofs) * 4u,
                         fpack2(h0, h1), peer_mbar);
            // output (unpadded global layout)
            *(float2*)(outp + (size_t)t * tstride) = make_float2(h0, h1);
            // prefetch next step's xp
            if (t + 1 < TT)
                xv = *(const float2*)(xpp + (size_t)(t + 1) * tstride);
        }

        __syncthreads();                            // publish local h CTA-wide
    }

    // Retire the final step's in-flight st.asyncs before the CTAs exit.
    mbar_wait_parity(((TT - 1) & 1) ? mb1 : mb0, ((TT - 1) >> 1) & 1u);
    CLUSTER_SYNC_();
}

// ---------------------------------------------------------------------------
// Launch
// ---------------------------------------------------------------------------
extern "C" void kernel_launch(void* const* d_in, const int* in_sizes, int n_in,
                              void* d_out, int out_size)
{
    const float* x    = (const float*)d_in[0];
    const float* Wih  = (const float*)d_in[1];
    const float* Whh  = (const float*)d_in[2];
    const float* b_ih = (const float*)d_in[3];
    const float* b_hh = (const float*)d_in[4];
    float* out = (float*)d_out;

    dim3 g1((TT * BB) / 128, HH / 128);
    xp_gemm_kernel<<<g1, 256>>>(x, Wih, b_ih, b_hh);

    rnn_scan_kernel<<<2 * BB, 512>>>(Whh, out);
}

// round 11
// speedup vs baseline: 1.4355x; 1.0110x over previous
#include <cuda_runtime.h>
#include <math.h>
#include <stdint.h>

#define TT 2048
#define BB 64
#define KIN 256
#define HH 256

typedef unsigned long long ull;

// Scratch for precomputed input projection xp[t][b][h] (134 MB device global).
__device__ float g_xp[(size_t)TT * BB * HH];

// ---------------------------------------------------------------------------
// f32x2 helpers (Blackwell packed fp32 pipe)
// ---------------------------------------------------------------------------
__device__ __forceinline__ ull ffma2(ull a, ull b, ull c) {
    ull d;
    asm("fma.rn.f32x2 %0, %1, %2, %3;" : "=l"(d) : "l"(a), "l"(b), "l"(c));
    return d;
}
__device__ __forceinline__ ull fdup2(float a) {
    ull d; unsigned u = __float_as_uint(a);
    asm("mov.b64 %0, {%1, %2};" : "=l"(d) : "r"(u), "r"(u));
    return d;
}
__device__ __forceinline__ ull fpack2(float a, float b) {
    ull d;
    asm("mov.b64 %0, {%1, %2};" : "=l"(d)
        : "r"(__float_as_uint(a)), "r"(__float_as_uint(b)));
    return d;
}
__device__ __forceinline__ float2 funpack2(ull a) {
    unsigned lo, hi;
    asm("mov.b64 {%0, %1}, %2;" : "=r"(lo), "=r"(hi) : "l"(a));
    return make_float2(__uint_as_float(lo), __uint_as_float(hi));
}
__device__ __forceinline__ uint32_t smem_u32(const void* p) {
    uint32_t a;
    asm("{ .reg .u64 t; cvta.to.shared.u64 t, %1; cvt.u32.u64 %0, t; }"
        : "=r"(a) : "l"(p));
    return a;
}
__device__ __forceinline__ uint32_t mapa_peer(uint32_t local, uint32_t peer) {
    uint32_t r;
    asm("mapa.shared::cluster.u32 %0, %1, %2;" : "=r"(r) : "r"(local), "r"(peer));
    return r;
}
__device__ __forceinline__ void st_async_b64(uint32_t raddr, ull v, uint32_t rbar) {
    asm volatile(
        "st.async.shared::cluster.mbarrier::complete_tx::bytes.b64 [%0], %1, [%2];"
        :: "r"(raddr), "l"(v), "r"(rbar) : "memory");
}
__device__ __forceinline__ void mbar_init(uint32_t addr, uint32_t cnt) {
    asm volatile("mbarrier.init.shared.b64 [%0], %1;" :: "r"(addr), "r"(cnt) : "memory");
}
__device__ __forceinline__ void mbar_expect_tx(uint32_t addr, uint32_t bytes) {
    asm volatile("mbarrier.arrive.expect_tx.shared.b64 _, [%0], %1;"
                 :: "r"(addr), "r"(bytes) : "memory");
}
__device__ __forceinline__ void mbar_wait_parity(uint32_t addr, uint32_t parity) {
    asm volatile(
        "{\n\t"
        ".reg .pred P;\n\t"
        "WL_%=:\n\t"
        "mbarrier.try_wait.parity.acquire.cluster.shared::cta.b64 P, [%0], %1, 0x989680;\n\t"
        "@!P bra WL_%=;\n\t"
        "}" :: "r"(addr), "r"(parity) : "memory");
}
#define CLUSTER_SYNC_() do { \
    asm volatile("barrier.cluster.arrive.aligned;" ::: "memory"); \
    asm volatile("barrier.cluster.wait.aligned;" ::: "memory"); \
} while (0)

// ---------------------------------------------------------------------------
// Kernel 1: xp[m][n] = x[m][:] . W_ih[n][:] + b_ih[n] + b_hh[n]   (f32x2 GEMM)
// (unchanged: proven)
// ---------------------------------------------------------------------------
__global__ __launch_bounds__(256, 2) void xp_gemm_kernel(
    const float* __restrict__ x,
    const float* __restrict__ Wih,
    const float* __restrict__ b_ih,
    const float* __restrict__ b_hh)
{
    __shared__ __align__(16) float As[16][132];
    __shared__ __align__(16) float Bs[16][132];

    const int tid = threadIdx.x;
    const int m0 = blockIdx.x * 128;
    const int n0 = blockIdx.y * 128;
    const int ty = tid >> 4;
    const int tx = tid & 15;

    ull acc[8][4];
#pragma unroll
    for (int i = 0; i < 8; i++)
#pragma unroll
        for (int p = 0; p < 4; p++) acc[i][p] = 0ull;

    for (int kt = 0; kt < KIN; kt += 16) {
#pragma unroll
        for (int l = 0; l < 2; l++) {
            int id  = tid + l * 256;
            int row = id >> 2;
            int c4  = (id & 3) * 4;
            float4 av = *(const float4*)(x   + (size_t)(m0 + row) * KIN + kt + c4);
            As[c4 + 0][row] = av.x; As[c4 + 1][row] = av.y;
            As[c4 + 2][row] = av.z; As[c4 + 3][row] = av.w;
            float4 bv = *(const float4*)(Wih + (size_t)(n0 + row) * KIN + kt + c4);
            Bs[c4 + 0][row] = bv.x; Bs[c4 + 1][row] = bv.y;
            Bs[c4 + 2][row] = bv.z; Bs[c4 + 3][row] = bv.w;
        }
        __syncthreads();

#pragma unroll
        for (int k = 0; k < 16; k++) {
            float4 a03 = *(const float4*)&As[k][ty * 8];
            float4 a47 = *(const float4*)&As[k][ty * 8 + 4];
            ulonglong2 bq0 = *(const ulonglong2*)&Bs[k][tx * 8];
            ulonglong2 bq1 = *(const ulonglong2*)&Bs[k][tx * 8 + 4];
            ull bp[4] = { bq0.x, bq0.y, bq1.x, bq1.y };
            float av[8] = { a03.x, a03.y, a03.z, a03.w, a47.x, a47.y, a47.z, a47.w };
#pragma unroll
            for (int i = 0; i < 8; i++) {
                ull ad = fdup2(av[i]);
#pragma unroll
                for (int p = 0; p < 4; p++)
                    acc[i][p] = ffma2(ad, bp[p], acc[i][p]);
            }
        }
        __syncthreads();
    }

    float bb[8];
#pragma unroll
    for (int j = 0; j < 8; j++) {
        int n = n0 + tx * 8 + j;
        bb[j] = b_ih[n] + b_hh[n];
    }
#pragma unroll
    for (int i = 0; i < 8; i++) {
        float* dst = g_xp + (size_t)(m0 + ty * 8 + i) * HH + n0 + tx * 8;
        float2 c0 = funpack2(acc[i][0]);
        float2 c1 = funpack2(acc[i][1]);
        float2 c2 = funpack2(acc[i][2]);
        float2 c3 = funpack2(acc[i][3]);
        float4 v0 = make_float4(c0.x + bb[0], c0.y + bb[1], c1.x + bb[2], c1.y + bb[3]);
        float4 v1 = make_float4(c2.x + bb[4], c2.y + bb[5], c3.x + bb[6], c3.y + bb[7]);
        *(float4*)dst       = v0;
        *(float4*)(dst + 4) = v1;
    }
}

// ---------------------------------------------------------------------------
// Kernel 2: serial recurrence, PARTIAL-SUM EXCHANGE topology.
// Cluster of 2 CTAs per batch (grid 128). CTA rank r keeps ONLY its own h
// half (rows [128r,128r+128)) locally; h never crosses CTAs. Per step each
// CTA computes partials P(j) = sum_{k in own half} W[j][k] h[k] for ALL
// 256 rows:
//   warps 0-7  (tid<256):  rows of the PEER  -> reduce -> st.async EARLY
//   warps 8-15 (tid>=256): rows of SELF      -> reduce -> wait peer partials
//                          -> add recv + xp -> tanh -> store own h half
// Lane (g = tid>>2, c = tid&3): rows (2gg, 2gg+1) of its target half,
// K-chunk [32c, 32c+32) of the CTA's own K half. W = 32 ull registers.
// Reduce: 2-round shfl.xor over the quad. Comm: 64 x 8 B st.async per step;
// two mbarriers alternated by t&1 (phase (t>>1)&1), double-buffered recv +
// double-buffered local h. h chunks padded to stride 36 -> conflict-free.
// ---------------------------------------------------------------------------
#define HP   36                       // padded chunk stride (floats)
#define HBUF (4 * HP)                 // 144 floats per local-h buffer
#define RBUF 128                      // recv partials per buffer

__global__ __launch_bounds__(512, 1) __cluster_dims__(2, 1, 1)
void rnn_scan_kernel(const float* __restrict__ Whh, float* __restrict__ out)
{
    __shared__ __align__(16) float hsm[2][HBUF];   // own h half, double-buffered
    __shared__ __align__(16) float rsm[2][RBUF];   // recv partials, double-buffered
    __shared__ __align__(8)  ull   mbars[2];

    const int tid = threadIdx.x;
    const unsigned rank = blockIdx.x & 1u;
    const int batch = blockIdx.x >> 1;
    const int c  = tid & 3;                     // K sub-chunk
    const int gg = (tid >> 2) & 63;             // row-pair index within half
    const bool peer_half = (tid < 256);         // warps 0-7: compute peer rows
    const int half_base = peer_half ? (int)((rank ^ 1u) * 128) : (int)(rank * 128);
    const int r0 = half_base + 2 * gg;          // target rows r0, r0+1
    const int k0 = (int)rank * 128 + 32 * c;    // own-K chunk

    const uint32_t mb0 = smem_u32(&mbars[0]);
    const uint32_t mb1 = smem_u32(&mbars[1]);
    const uint32_t rsm_addr = smem_u32(&rsm[0][0]);
    const uint32_t peer = rank ^ 1u;
    const uint32_t peer_mb0 = mapa_peer(mb0, peer);
    const uint32_t peer_mb1 = mapa_peer(mb1, peer);
    const uint32_t peer_rsm = mapa_peer(rsm_addr, peer);

    // Register-resident W: rows r0, r0+1 x K-chunk [k0, k0+32) as f32x2 pairs.
    ull w0[16], w1[16];
    {
        const ull* p0 = (const ull*)(Whh + (size_t)r0 * HH + k0);
        const ull* p1 = (const ull*)(Whh + (size_t)(r0 + 1) * HH + k0);
#pragma unroll
        for (int i = 0; i < 16; i++) { w0[i] = p0[i]; w1[i] = p1[i]; }
    }

    if (tid < HBUF) hsm[0][tid] = 0.0f;         // h_{-1} = 0 (own half)
    if (tid == 0) { mbar_init(mb0, 1); mbar_init(mb1, 1); }
    __syncthreads();
    CLUSTER_SYNC_();                             // peer mbars visible

    const size_t tstride = (size_t)BB * HH;
    // xp / out pointers: only meaningful for own-half c==0 lanes.
    const float* xpp  = g_xp + (size_t)batch * HH + r0;
    float*       outp = out  + (size_t)batch * HH + r0;

    float2 xv = make_float2(0.f, 0.f);
    if (!peer_half && c == 0) xv = *(const float2*)xpp;   // xp for t = 0

    for (int t = 0; t < TT; t++) {
        const unsigned par = (unsigned)t & 1u;
        const uint32_t mbar      = par ? mb1 : mb0;
        const uint32_t peer_mbar = par ? peer_mb1 : peer_mb0;
        const unsigned phase     = ((unsigned)t >> 1) & 1u;

        if (tid == 0) mbar_expect_tx(mbar, 512);   // 64 x 8 B from peer, step t

        // Partial dot over own-K chunk [32c, 32c+32): rows r0, r0+1.
        const ulonglong2* hp = (const ulonglong2*)&hsm[par][HP * c];
        ull a0 = 0ull, a1 = 0ull;
#pragma unroll
        for (int i = 0; i < 8; i++) {
            ulonglong2 hq = hp[i];
            a0 = ffma2(w0[2 * i],     hq.x, a0);
            a1 = ffma2(w1[2 * i],     hq.x, a1);
            a0 = ffma2(w0[2 * i + 1], hq.y, a0);
            a1 = ffma2(w1[2 * i + 1], hq.y, a1);
        }
        float2 u0 = funpack2(a0), u1 = funpack2(a1);
        float s0 = u0.x + u0.y;
        float s1 = u1.x + u1.y;
#pragma unroll
        for (int m = 1; m < 4; m <<= 1) {
            s0 += __shfl_xor_sync(0xffffffffu, s0, m);
            s1 += __shfl_xor_sync(0xffffffffu, s1, m);
        }

        if (peer_half) {
            // Send partials for peer's rows EARLY (flight overlaps peer's work).
            if (c == 0) {
                uint32_t raddr = peer_rsm + (par * (unsigned)RBUF + 2u * (unsigned)gg) * 4u;
                st_async_b64(raddr, fpack2(s0, s1), peer_mbar);
            }
        } else {
            // Own rows: wait for peer partials of THIS step, combine, tanh.
            mbar_wait_parity(mbar, phase);
            if (c == 0) {
                float2 pr = *(const float2*)&rsm[par][2 * gg];
                float h0 = tanhf(s0 + pr.x + xv.x);
                float h1 = tanhf(s1 + pr.y + xv.y);
                const unsigned nb = par ^ 1u;
                const int li = 2 * gg;              // local h index (even)
                hsm[nb][HP * (li >> 5) + (li & 31)]     = h0;
                hsm[nb][HP * (li >> 5) + (li & 31) + 1] = h1;
                *(float2*)(outp + (size_t)t * tstride) = make_float2(h0, h1);
                if (t + 1 < TT)
                    xv = *(const float2*)(xpp + (size_t)(t + 1) * tstride);
            }
        }

        __syncthreads();   // new own-h half visible CTA-wide; rsm[par] retired
    }
    CLUSTER_SYNC_();
}

// ---------------------------------------------------------------------------
// Launch
// ---------------------------------------------------------------------------
extern "C" void kernel_launch(void* const* d_in, const int* in_sizes, int n_in,
                              void* d_out, int out_size)
{
    const float* x    = (const float*)d_in[0];
    const float* Wih  = (const float*)d_in[1];
    const float* Whh  = (const float*)d_in[2];
    const float* b_ih = (const float*)d_in[3];
    const float* b_hh = (const float*)d_in[4];
    float* out = (float*)d_out;

    dim3 g1((TT * BB) / 128, HH / 128);
    xp_gemm_kernel<<<g1, 256>>>(x, Wih, b_ih, b_hh);

    rnn_scan_kernel<<<2 * BB, 512>>>(Whh, out);
}

// round 12
// speedup vs baseline: 1.4480x; 1.0088x over previous
#include <cuda_runtime.h>
#include <math.h>
#include <stdint.h>

#define TT 2048
#define BB 64
#define KIN 256
#define HH 256

typedef unsigned long long ull;

// Scratch for precomputed input projection xp[t][b][h] (134 MB device global).
__device__ float g_xp[(size_t)TT * BB * HH];

// ---------------------------------------------------------------------------
// f32x2 helpers (Blackwell packed fp32 pipe)
// ---------------------------------------------------------------------------
__device__ __forceinline__ ull ffma2(ull a, ull b, ull c) {
    ull d;
    asm("fma.rn.f32x2 %0, %1, %2, %3;" : "=l"(d) : "l"(a), "l"(b), "l"(c));
    return d;
}
__device__ __forceinline__ ull fadd2(ull a, ull b) {
    ull d;
    asm("add.rn.f32x2 %0, %1, %2;" : "=l"(d) : "l"(a), "l"(b));
    return d;
}
__device__ __forceinline__ ull fdup2(float a) {
    ull d; unsigned u = __float_as_uint(a);
    asm("mov.b64 %0, {%1, %2};" : "=l"(d) : "r"(u), "r"(u));
    return d;
}
__device__ __forceinline__ ull fpack2(float a, float b) {
    ull d;
    asm("mov.b64 %0, {%1, %2};" : "=l"(d)
        : "r"(__float_as_uint(a)), "r"(__float_as_uint(b)));
    return d;
}
__device__ __forceinline__ float2 funpack2(ull a) {
    unsigned lo, hi;
    asm("mov.b64 {%0, %1}, %2;" : "=r"(lo), "=r"(hi) : "l"(a));
    return make_float2(__uint_as_float(lo), __uint_as_float(hi));
}
__device__ __forceinline__ uint32_t smem_u32(const void* p) {
    uint32_t a;
    asm("{ .reg .u64 t; cvta.to.shared.u64 t, %1; cvt.u32.u64 %0, t; }"
        : "=r"(a) : "l"(p));
    return a;
}
__device__ __forceinline__ uint32_t mapa_peer(uint32_t local, uint32_t peer) {
    uint32_t r;
    asm("mapa.shared::cluster.u32 %0, %1, %2;" : "=r"(r) : "r"(local), "r"(peer));
    return r;
}
__device__ __forceinline__ void st_async_b64(uint32_t raddr, ull v, uint32_t rbar) {
    asm volatile(
        "st.async.shared::cluster.mbarrier::complete_tx::bytes.b64 [%0], %1, [%2];"
        :: "r"(raddr), "l"(v), "r"(rbar) : "memory");
}
__device__ __forceinline__ void mbar_init(uint32_t addr, uint32_t cnt) {
    asm volatile("mbarrier.init.shared.b64 [%0], %1;" :: "r"(addr), "r"(cnt) : "memory");
}
__device__ __forceinline__ void mbar_expect_tx(uint32_t addr, uint32_t bytes) {
    asm volatile("mbarrier.arrive.expect_tx.shared.b64 _, [%0], %1;"
                 :: "r"(addr), "r"(bytes) : "memory");
}
__device__ __forceinline__ void mbar_wait_parity(uint32_t addr, uint32_t parity) {
    asm volatile(
        "{\n\t"
        ".reg .pred P;\n\t"
        "WL_%=:\n\t"
        "mbarrier.try_wait.parity.acquire.cluster.shared::cta.b64 P, [%0], %1, 0x989680;\n\t"
        "@!P bra WL_%=;\n\t"
        "}" :: "r"(addr), "r"(parity) : "memory");
}
#define CLUSTER_SYNC_() do { \
    asm volatile("barrier.cluster.arrive.aligned;" ::: "memory"); \
    asm volatile("barrier.cluster.wait.aligned;" ::: "memory"); \
} while (0)

// ---------------------------------------------------------------------------
// Kernel 1: xp[m][n] = x[m][:] . W_ih[n][:] + b_ih[n] + b_hh[n]   (f32x2 GEMM)
// (unchanged: proven)
// ---------------------------------------------------------------------------
__global__ __launch_bounds__(256, 2) void xp_gemm_kernel(
    const float* __restrict__ x,
    const float* __restrict__ Wih,
    const float* __restrict__ b_ih,
    const float* __restrict__ b_hh)
{
    __shared__ __align__(16) float As[16][132];
    __shared__ __align__(16) float Bs[16][132];

    const int tid = threadIdx.x;
    const int m0 = blockIdx.x * 128;
    const int n0 = blockIdx.y * 128;
    const int ty = tid >> 4;
    const int tx = tid & 15;

    ull acc[8][4];
#pragma unroll
    for (int i = 0; i < 8; i++)
#pragma unroll
        for (int p = 0; p < 4; p++) acc[i][p] = 0ull;

    for (int kt = 0; kt < KIN; kt += 16) {
#pragma unroll
        for (int l = 0; l < 2; l++) {
            int id  = tid + l * 256;
            int row = id >> 2;
            int c4  = (id & 3) * 4;
            float4 av = *(const float4*)(x   + (size_t)(m0 + row) * KIN + kt + c4);
            As[c4 + 0][row] = av.x; As[c4 + 1][row] = av.y;
            As[c4 + 2][row] = av.z; As[c4 + 3][row] = av.w;
            float4 bv = *(const float4*)(Wih + (size_t)(n0 + row) * KIN + kt + c4);
            Bs[c4 + 0][row] = bv.x; Bs[c4 + 1][row] = bv.y;
            Bs[c4 + 2][row] = bv.z; Bs[c4 + 3][row] = bv.w;
        }
        __syncthreads();

#pragma unroll
        for (int k = 0; k < 16; k++) {
            float4 a03 = *(const float4*)&As[k][ty * 8];
            float4 a47 = *(const float4*)&As[k][ty * 8 + 4];
            ulonglong2 bq0 = *(const ulonglong2*)&Bs[k][tx * 8];
            ulonglong2 bq1 = *(const ulonglong2*)&Bs[k][tx * 8 + 4];
            ull bp[4] = { bq0.x, bq0.y, bq1.x, bq1.y };
            float av[8] = { a03.x, a03.y, a03.z, a03.w, a47.x, a47.y, a47.z, a47.w };
#pragma unroll
            for (int i = 0; i < 8; i++) {
                ull ad = fdup2(av[i]);
#pragma unroll
                for (int p = 0; p < 4; p++)
                    acc[i][p] = ffma2(ad, bp[p], acc[i][p]);
            }
        }
        __syncthreads();
    }

    float bb[8];
#pragma unroll
    for (int j = 0; j < 8; j++) {
        int n = n0 + tx * 8 + j;
        bb[j] = b_ih[n] + b_hh[n];
    }
#pragma unroll
    for (int i = 0; i < 8; i++) {
        float* dst = g_xp + (size_t)(m0 + ty * 8 + i) * HH + n0 + tx * 8;
        float2 c0 = funpack2(acc[i][0]);
        float2 c1 = funpack2(acc[i][1]);
        float2 c2 = funpack2(acc[i][2]);
        float2 c3 = funpack2(acc[i][3]);
        float4 v0 = make_float4(c0.x + bb[0], c0.y + bb[1], c1.x + bb[2], c1.y + bb[3]);
        float4 v1 = make_float4(c2.x + bb[4], c2.y + bb[5], c3.x + bb[6], c3.y + bb[7]);
        *(float4*)dst       = v0;
        *(float4*)(dst + 4) = v1;
    }
}

// ---------------------------------------------------------------------------
// Kernel 2: serial recurrence, partial-sum exchange (round-11 protocol) with
// latency trims:
//   - SENDERS are the HIGH warps 8-15 (arbiter is hi-wid-first -> earlier send)
//   - RECEIVERS (own rows) are warps 0-7
//   - tanh/store split across lanes c==0 (row r0) and c==1 (row r0+1)
//   - two f32x2 accumulators per row (K 16+16) -> ~half the FFMA2 dep chain
//   - only c<2 receiver lanes execute the mbarrier wait
// Comm: 64 x 8 B st.async per step; two mbarriers alternated by t&1, phase
// (t>>1)&1; double-buffered recv + double-buffered local h half.
// h chunks padded to stride 36 -> conflict-free LDS.128.
// ---------------------------------------------------------------------------
#define HP   36                       // padded chunk stride (floats)
#define HBUF (4 * HP)                 // 144 floats per local-h buffer
#define RBUF 128                      // recv partials per buffer

__global__ __launch_bounds__(512, 1) __cluster_dims__(2, 1, 1)
void rnn_scan_kernel(const float* __restrict__ Whh, float* __restrict__ out)
{
    __shared__ __align__(16) float hsm[2][HBUF];   // own h half, double-buffered
    __shared__ __align__(16) float rsm[2][RBUF];   // recv partials, double-buffered
    __shared__ __align__(8)  ull   mbars[2];

    const int tid = threadIdx.x;
    const unsigned rank = blockIdx.x & 1u;
    const int batch = blockIdx.x >> 1;
    const int c  = tid & 3;                     // K sub-chunk / role lane
    const int gg = (tid >> 2) & 63;             // row-pair index within half
    const bool sender = (tid >= 256);           // warps 8-15: compute peer rows
    const int half_base = sender ? (int)((rank ^ 1u) * 128) : (int)(rank * 128);
    const int r0 = half_base + 2 * gg;          // target rows r0, r0+1
    const int k0 = (int)rank * 128 + 32 * c;    // own-K chunk

    const uint32_t mb0 = smem_u32(&mbars[0]);
    const uint32_t mb1 = smem_u32(&mbars[1]);
    const uint32_t rsm_addr = smem_u32(&rsm[0][0]);
    const uint32_t peer = rank ^ 1u;
    const uint32_t peer_mb0 = mapa_peer(mb0, peer);
    const uint32_t peer_mb1 = mapa_peer(mb1, peer);
    const uint32_t peer_rsm = mapa_peer(rsm_addr, peer);

    // Register-resident W: rows r0, r0+1 x K-chunk [k0, k0+32) as f32x2 pairs.
    ull w0[16], w1[16];
    {
        const ull* p0 = (const ull*)(Whh + (size_t)r0 * HH + k0);
        const ull* p1 = (const ull*)(Whh + (size_t)(r0 + 1) * HH + k0);
#pragma unroll
        for (int i = 0; i < 16; i++) { w0[i] = p0[i]; w1[i] = p1[i]; }
    }

    if (tid < HBUF) hsm[0][tid] = 0.0f;         // h_{-1} = 0 (own half)
    if (tid == 0) { mbar_init(mb0, 1); mbar_init(mb1, 1); }
    __syncthreads();
    CLUSTER_SYNC_();                             // peer mbars visible

    const size_t tstride = (size_t)BB * HH;
    // Receiver per-lane scalar row (c < 2): row r0 + c.
    const float* xpp  = g_xp + (size_t)batch * HH + r0 + c;
    float*       outp = out  + (size_t)batch * HH + r0 + c;

    float xv = 0.0f;
    if (!sender && c < 2) xv = *xpp;            // xp for t = 0

    for (int t = 0; t < TT; t++) {
        const unsigned par = (unsigned)t & 1u;
        const uint32_t mbar      = par ? mb1 : mb0;
        const uint32_t peer_mbar = par ? peer_mb1 : peer_mb0;
        const unsigned phase     = ((unsigned)t >> 1) & 1u;

        if (tid == 0) mbar_expect_tx(mbar, 512);   // 64 x 8 B from peer, step t

        // Partial dot over own-K chunk [32c, 32c+32): rows r0, r0+1.
        // Two accumulators per row (K 16+16) -> shorter dep chains.
        const ulonglong2* hp = (const ulonglong2*)&hsm[par][HP * c];
        ull a0A = 0ull, a1A = 0ull, a0B = 0ull, a1B = 0ull;
#pragma unroll
        for (int i = 0; i < 4; i++) {
            ulonglong2 hq = hp[i];
            a0A = ffma2(w0[2 * i],     hq.x, a0A);
            a1A = ffma2(w1[2 * i],     hq.x, a1A);
            a0A = ffma2(w0[2 * i + 1], hq.y, a0A);
            a1A = ffma2(w1[2 * i + 1], hq.y, a1A);
        }
#pragma unroll
        for (int i = 4; i < 8; i++) {
            ulonglong2 hq = hp[i];
            a0B = ffma2(w0[2 * i],     hq.x, a0B);
            a1B = ffma2(w1[2 * i],     hq.x, a1B);
            a0B = ffma2(w0[2 * i + 1], hq.y, a0B);
            a1B = ffma2(w1[2 * i + 1], hq.y, a1B);
        }
        float2 u0 = funpack2(fadd2(a0A, a0B));
        float2 u1 = funpack2(fadd2(a1A, a1B));
        float s0 = u0.x + u0.y;
        float s1 = u1.x + u1.y;
#pragma unroll
        for (int m = 1; m < 4; m <<= 1) {
            s0 += __shfl_xor_sync(0xffffffffu, s0, m);
            s1 += __shfl_xor_sync(0xffffffffu, s1, m);
        }

        if (sender) {
            // Send partials for peer's rows EARLY (hi-wid warps issue first).
            if (c == 0) {
                uint32_t raddr = peer_rsm + (par * (unsigned)RBUF + 2u * (unsigned)gg) * 4u;
                st_async_b64(raddr, fpack2(s0, s1), peer_mbar);
            }
        } else if (c < 2) {
            // Own rows: wait for peer partials of THIS step, combine, tanh.
            // Lane c handles row r0 + c (serial tanh halved vs single lane).
            mbar_wait_parity(mbar, phase);
            const int li = 2 * gg + c;              // local h index
            float pr = rsm[par][li];
            float hn = tanhf((c ? s1 : s0) + pr + xv);
            const unsigned nb = par ^ 1u;
            hsm[nb][HP * (li >> 5) + (li & 31)] = hn;
            outp[(size_t)t * tstride] = hn;
            if (t + 1 < TT)
                xv = xpp[(size_t)(t + 1) * tstride];
        }

        __syncthreads();   // new own-h half visible CTA-wide; rsm[par] retired
    }
    CLUSTER_SYNC_();
}

// ---------------------------------------------------------------------------
// Launch
// ---------------------------------------------------------------------------
extern "C" void kernel_launch(void* const* d_in, const int* in_sizes, int n_in,
                              void* d_out, int out_size)
{
    const float* x    = (const float*)d_in[0];
    const float* Wih  = (const float*)d_in[1];
    const float* Whh  = (const float*)d_in[2];
    const float* b_ih = (const float*)d_in[3];
    const float* b_hh = (const float*)d_in[4];
    float* out = (float*)d_out;

    dim3 g1((TT * BB) / 128, HH / 128);
    xp_gemm_kernel<<<g1, 256>>>(x, Wih, b_ih, b_hh);

    rnn_scan_kernel<<<2 * BB, 512>>>(Whh, out);
}